// round 6
// baseline (speedup 1.0000x reference)
#include <cuda_runtime.h>

// Problem constants
#define Bn 16
#define Jn 16
#define Cn 64
#define Hn 256
#define Wn 256
#define HWn (Hn * Wn)          // 65536
#define SPLIT 8
#define CHUNK (HWn / SPLIT)    // 8192 floats per split-block
#define NPART (Bn * Jn * SPLIT)      // 2048
#define BLKS_PER_B (Jn * SPLIT)      // 128 blocks feed each batch
#define QPT (CHUNK / 4 / 256)        // 8 float4s per thread

#define NEG_INF (-3.4028235e38f)

// Scratch (device globals: allocation-free). g_count starts zeroed; each
// finalizer resets its slot so graph replays are deterministic.
__device__ float g_pval[NPART];
__device__ int   g_pidx[NPART];
__device__ int   g_count[Bn];

// ---------------------------------------------------------------------------
// Fused kernel: split-K argmax (max-then-find) + last-block-per-batch finalize
// grid = B*J*SPLIT = 2048 blocks, 256 threads.
// ---------------------------------------------------------------------------
__global__ __launch_bounds__(256) void fused_labelloss_kernel(
    const float* __restrict__ heatmap,
    const float* __restrict__ pred,
    const float* __restrict__ gt,
    float* __restrict__ out)
{
    const int blk = blockIdx.x;
    const int bj  = blk / SPLIT;         // 0..255  (= b*Jn + j)
    const int s   = blk % SPLIT;
    const int b   = bj / Jn;
    const int t   = threadIdx.x;
    const int wid = t >> 5, lid = t & 31;

    const float4* __restrict__ src = reinterpret_cast<const float4*>(
        heatmap + (size_t)bj * HWn + (size_t)s * CHUNK);

    // -------- Pass 1: pure max (1 FMNMX/elem, short dependency chains) ------
    float qm[QPT];      // per-quad maxes, register resident (8 regs)
    float m = NEG_INF;

    #pragma unroll
    for (int it = 0; it < QPT; ++it) {
        const float4 v = __ldg(&src[t + it * 256]);
        qm[it] = fmaxf(fmaxf(v.x, v.y), fmaxf(v.z, v.w));
        m = fmaxf(m, qm[it]);
    }

    // warp max (xor butterfly)
    #pragma unroll
    for (int off = 16; off > 0; off >>= 1)
        m = fmaxf(m, __shfl_xor_sync(0xffffffff, m, off));

    __shared__ float swm[8];
    __shared__ float s_bmax;
    __shared__ int   s_bidx;
    __shared__ int   s_last;

    if (lid == 0) swm[wid] = m;
    if (t == 0)   s_bidx = 0x7fffffff;
    __syncthreads();

    if (t < 32) {
        float mm = (t < 8) ? swm[t] : NEG_INF;
        #pragma unroll
        for (int off = 4; off > 0; off >>= 1)
            mm = fmaxf(mm, __shfl_xor_sync(0xffffffff, mm, off));
        if (t == 0) s_bmax = mm;
    }
    __syncthreads();

    const float bmax = s_bmax;

    // -------- Pass 2: find first (lowest flat index) occurrence of bmax -----
    // Register compares only; drill-down reload (L1-hot) on ~1 thread/block.
    #pragma unroll
    for (int it = 0; it < QPT; ++it) {
        if (qm[it] == bmax) {
            const int p = t + it * 256;
            const float4 v = __ldg(&src[p]);
            const int base = s * CHUNK + p * 4;
            if (v.x == bmax) atomicMin(&s_bidx, base + 0);
            if (v.y == bmax) atomicMin(&s_bidx, base + 1);
            if (v.z == bmax) atomicMin(&s_bidx, base + 2);
            if (v.w == bmax) atomicMin(&s_bidx, base + 3);
        }
    }
    __syncthreads();

    // -------- Publish partial; 128th arriver per batch finalizes ------------
    if (t == 0) {
        g_pval[bj * SPLIT + s] = bmax;
        g_pidx[bj * SPLIT + s] = s_bidx;
        __threadfence();
        const int prev = atomicAdd(&g_count[b], 1);
        s_last = (prev == BLKS_PER_B - 1) ? 1 : 0;
    }
    __syncthreads();

    if (!s_last) return;

    // ------------------- Finalize batch b: gather + MSE ---------------------
    __shared__ int s_idx[Jn];

    if (t < Jn) {
        const int base = (b * Jn + t) * SPLIT;
        float bv = NEG_INF;
        int   bi = 0x7fffffff;
        #pragma unroll
        for (int k = 0; k < SPLIT; ++k) {
            const float v = __ldcg(&g_pval[base + k]);
            const int   i = __ldcg(&g_pidx[base + k]);
            if (v > bv || (v == bv && i < bi)) { bv = v; bi = i; }
        }
        s_idx[t] = bi;
    }
    __syncthreads();

    // J*C = 1024 gathered elements, 256 threads -> 4 each
    float acc = 0.0f;
    #pragma unroll
    for (int it = 0; it < (Jn * Cn) / 256; ++it) {
        const int e = t + it * 256;
        const int j = e >> 6;        // /64
        const int c = e & 63;        // %64
        const int idx = s_idx[j];
        const float p = __ldg(&pred[((size_t)b * Cn + c) * HWn + idx]);
        const float g = __ldg(&gt[((size_t)b * Jn + j) * Cn + c]);
        const float d = p - g;
        acc += d * d;
    }

    #pragma unroll
    for (int off = 16; off > 0; off >>= 1)
        acc += __shfl_down_sync(0xffffffff, acc, off);

    __shared__ float ss[8];
    if (lid == 0) ss[wid] = acc;
    __syncthreads();
    if (t < 32) {
        acc = (lid < 8) ? ss[lid] : 0.0f;
        #pragma unroll
        for (int off = 4; off > 0; off >>= 1)
            acc += __shfl_down_sync(0xffffffff, acc, off);
        if (lid == 0) {
            out[b] = acc * (1.0f / (Jn * Cn));
            g_count[b] = 0;   // reset for next graph replay
        }
    }
}

extern "C" void kernel_launch(void* const* d_in, const int* in_sizes, int n_in,
                              void* d_out, int out_size)
{
    const float* pred    = (const float*)d_in[0];   // [B,C,H,W]
    const float* gt      = (const float*)d_in[1];   // [B,J,C]
    const float* heatmap = (const float*)d_in[2];   // [B,J,H,W]
    float* out = (float*)d_out;                     // [B]

    fused_labelloss_kernel<<<NPART, 256>>>(heatmap, pred, gt, out);
}

// round 7
// speedup vs baseline: 1.1214x; 1.1214x over previous
#include <cuda_runtime.h>
#include <cstdint>

// Problem constants
#define Bn 16
#define Jn 16
#define Cn 64
#define HWn 65536                 // 256*256
#define SPLIT 8
#define CHUNK (HWn / SPLIT)       // 8192 floats = 32 KB per block
#define NPART (Bn * Jn * SPLIT)   // 2048 blocks
#define BLKS_PER_B (Jn * SPLIT)   // 128 blocks feed each batch
#define QPT (CHUNK / 4 / 256)     // 8 float4s per thread

#define NEG_INF (-3.4028235e38f)

// Scratch (device globals: allocation-free). g_count starts zeroed; each
// finalizer resets its slot so graph replays are deterministic.
__device__ float g_pval[NPART];
__device__ int   g_pidx[NPART];
__device__ int   g_count[Bn];

__device__ __forceinline__ uint32_t smem_u32(const void* p) {
    uint32_t a;
    asm("{ .reg .u64 t; cvta.to.shared.u64 t, %1; cvt.u32.u64 %0, t; }"
        : "=r"(a) : "l"(p));
    return a;
}

// ---------------------------------------------------------------------------
// Fused kernel: bulk-async stage to SMEM -> max scan -> filtered index rescan
// -> last-block-per-batch finalize. grid = 2048 blocks, 256 threads.
// ---------------------------------------------------------------------------
__global__ __launch_bounds__(256) void fused_labelloss_kernel(
    const float* __restrict__ heatmap,
    const float* __restrict__ pred,
    const float* __restrict__ gt,
    float* __restrict__ out)
{
    __shared__ alignas(128) float tile[CHUNK];          // 32 KB staging
    __shared__ alignas(8) unsigned long long mbar;
    __shared__ float swm[8];
    __shared__ float s_bmax;
    __shared__ int   s_bidx;
    __shared__ int   s_last;

    const int blk = blockIdx.x;
    const int bj  = blk / SPLIT;          // b*Jn + j
    const int s   = blk % SPLIT;
    const int b   = bj / Jn;
    const int t   = threadIdx.x;
    const int wid = t >> 5, lid = t & 31;

    const float* src = heatmap + (size_t)bj * HWn + (size_t)s * CHUNK;
    const uint32_t mb = smem_u32(&mbar);
    const uint32_t tl = smem_u32(tile);

    // ---- Stage chunk into SMEM with one bulk async copy (UBLKCP) ----------
    if (t == 0) {
        asm volatile("mbarrier.init.shared.b64 [%0], %1;"
                     :: "r"(mb), "r"(1) : "memory");
        asm volatile("fence.proxy.async.shared::cta;" ::: "memory");
        s_bidx = 0x7fffffff;
    }
    __syncthreads();     // mbarrier init visible to all before any wait
    if (t == 0) {
        asm volatile("mbarrier.arrive.expect_tx.shared.b64 _, [%0], %1;"
                     :: "r"(mb), "r"(CHUNK * 4) : "memory");
        asm volatile(
            "cp.async.bulk.shared::cta.global.mbarrier::complete_tx::bytes "
            "[%0], [%1], %2, [%3];"
            :: "r"(tl), "l"(src), "r"(CHUNK * 4), "r"(mb) : "memory");
    }

    // Wait for copy completion (parity 0, acquire orders LDS after TMA write)
    {
        uint32_t done;
        asm volatile(
            "{\n\t.reg .pred p;\n\t"
            "mbarrier.try_wait.parity.acquire.cta.shared::cta.b64 p, [%1], %2;\n\t"
            "selp.b32 %0, 1, 0, p;\n\t}"
            : "=r"(done) : "r"(mb), "r"(0) : "memory");
        if (!done) {
            asm volatile(
                "{\n\t.reg .pred P1;\n\t"
                "W%=:\n\t"
                "mbarrier.try_wait.parity.acquire.cta.shared::cta.b64 P1, [%0], %1;\n\t"
                "@P1 bra.uni D%=;\n\t"
                "bra.uni W%=;\n\t"
                "D%=:\n\t}"
                :: "r"(mb), "r"(0) : "memory");
        }
    }

    // ---- Pass 1: pure max over SMEM (1 FMNMX/elem, no index tracking) ------
    const float4* __restrict__ tq = reinterpret_cast<const float4*>(tile);
    float m = NEG_INF;
    #pragma unroll
    for (int it = 0; it < QPT; ++it) {
        const float4 v = tq[t + it * 256];
        m = fmaxf(m, fmaxf(fmaxf(v.x, v.y), fmaxf(v.z, v.w)));
    }

    #pragma unroll
    for (int off = 16; off > 0; off >>= 1)
        m = fmaxf(m, __shfl_xor_sync(0xffffffff, m, off));

    if (lid == 0) swm[wid] = m;
    __syncthreads();

    if (t < 32) {
        float mm = (t < 8) ? swm[t] : NEG_INF;
        #pragma unroll
        for (int off = 4; off > 0; off >>= 1)
            mm = fmaxf(mm, __shfl_xor_sync(0xffffffff, mm, off));
        if (t == 0) s_bmax = mm;
    }
    __syncthreads();

    const float bmax = s_bmax;

    // ---- Pass 2: only winning warp(s) rescan their SMEM slice --------------
    if (swm[wid] == bmax) {
        #pragma unroll
        for (int it = 0; it < QPT; ++it) {
            const int p = t + it * 256;
            const float4 v = tq[p];
            const int base = s * CHUNK + p * 4;
            if (v.x == bmax) atomicMin(&s_bidx, base + 0);
            if (v.y == bmax) atomicMin(&s_bidx, base + 1);
            if (v.z == bmax) atomicMin(&s_bidx, base + 2);
            if (v.w == bmax) atomicMin(&s_bidx, base + 3);
        }
    }
    __syncthreads();

    // ---- Publish partial; last arriver per batch finalizes -----------------
    if (t == 0) {
        g_pval[bj * SPLIT + s] = bmax;
        g_pidx[bj * SPLIT + s] = s_bidx;
        __threadfence();
        const int prev = atomicAdd(&g_count[b], 1);
        s_last = (prev == BLKS_PER_B - 1) ? 1 : 0;
    }
    __syncthreads();

    if (!s_last) return;

    // ------------------- Finalize batch b: gather + MSE ---------------------
    __shared__ int s_idx[Jn];

    if (t < Jn) {
        const int base = (b * Jn + t) * SPLIT;
        float bv = NEG_INF;
        int   bi = 0x7fffffff;
        #pragma unroll
        for (int k = 0; k < SPLIT; ++k) {
            const float v = __ldcg(&g_pval[base + k]);
            const int   i = __ldcg(&g_pidx[base + k]);
            if (v > bv || (v == bv && i < bi)) { bv = v; bi = i; }
        }
        s_idx[t] = bi;
    }
    __syncthreads();

    // J*C = 1024 gathered elements, 256 threads -> 4 each
    float acc = 0.0f;
    #pragma unroll
    for (int it = 0; it < (Jn * Cn) / 256; ++it) {
        const int e = t + it * 256;
        const int j = e >> 6;        // /64
        const int c = e & 63;        // %64
        const int idx = s_idx[j];
        const float p = __ldg(&pred[((size_t)b * Cn + c) * HWn + idx]);
        const float g = __ldg(&gt[((size_t)b * Jn + j) * Cn + c]);
        const float d = p - g;
        acc += d * d;
    }

    #pragma unroll
    for (int off = 16; off > 0; off >>= 1)
        acc += __shfl_down_sync(0xffffffff, acc, off);

    __shared__ float ss[8];
    if (lid == 0) ss[wid] = acc;
    __syncthreads();
    if (t < 32) {
        acc = (lid < 8) ? ss[lid] : 0.0f;
        #pragma unroll
        for (int off = 4; off > 0; off >>= 1)
            acc += __shfl_down_sync(0xffffffff, acc, off);
        if (lid == 0) {
            out[b] = acc * (1.0f / (Jn * Cn));
            g_count[b] = 0;   // reset for next graph replay
        }
    }
}

extern "C" void kernel_launch(void* const* d_in, const int* in_sizes, int n_in,
                              void* d_out, int out_size)
{
    const float* pred    = (const float*)d_in[0];   // [B,C,H,W]
    const float* gt      = (const float*)d_in[1];   // [B,J,C]
    const float* heatmap = (const float*)d_in[2];   // [B,J,H,W]
    float* out = (float*)d_out;                     // [B]

    fused_labelloss_kernel<<<NPART, 256>>>(heatmap, pred, gt, out);
}

// round 9
// speedup vs baseline: 1.4108x; 1.2581x over previous
#include <cuda_runtime.h>
#include <cstdint>

// Problem constants
#define Bn 16
#define Jn 16
#define Cn 64
#define HWn 65536                 // 256*256
#define SPLIT 4
#define CHUNK (HWn / SPLIT)       // 16384 floats per split-block
#define NPART (Bn * Jn * SPLIT)   // 1024 blocks
#define BLKS_PER_B (Jn * SPLIT)   // 64 blocks feed each batch
#define QPT (CHUNK / 4 / 256)     // 16 float4s per thread

#define NEG_INF (-3.4028235e38f)

// Scratch (device globals: allocation-free). g_count starts zeroed; each
// finalizer resets its slot so graph replays are deterministic.
__device__ float g_pval[NPART];
__device__ int   g_pidx[NPART];
__device__ int   g_count[Bn];

// ---------------------------------------------------------------------------
// Fused kernel: streaming max scan (no index) -> winning-warp index rescan
// -> last-block-per-batch finalize. grid = 1024 blocks, 256 threads.
// ---------------------------------------------------------------------------
__global__ __launch_bounds__(256) void fused_labelloss_kernel(
    const float* __restrict__ heatmap,
    const float* __restrict__ pred,
    const float* __restrict__ gt,
    float* __restrict__ out)
{
    const int blk = blockIdx.x;
    const int bj  = blk / SPLIT;         // b*Jn + j
    const int s   = blk % SPLIT;
    const int b   = bj / Jn;
    const int t   = threadIdx.x;
    const int wid = t >> 5, lid = t & 31;

    const float4* __restrict__ src = reinterpret_cast<const float4*>(
        heatmap + (size_t)bj * HWn + (size_t)s * CHUNK);

    __shared__ float swm[8];
    __shared__ float s_bmax;
    __shared__ int   s_bidx;
    __shared__ int   s_last;

    if (t == 0) s_bidx = 0x7fffffff;

    // -------- Pass 1: pure running max (4 FMNMX/quad, 1 reg of state) -------
    float m = NEG_INF;
    #pragma unroll
    for (int it = 0; it < QPT; ++it) {
        const float4 v = __ldg(&src[t + it * 256]);
        m = fmaxf(m, fmaxf(fmaxf(v.x, v.y), fmaxf(v.z, v.w)));
    }

    // warp max (xor butterfly: all lanes get warp max)
    #pragma unroll
    for (int off = 16; off > 0; off >>= 1)
        m = fmaxf(m, __shfl_xor_sync(0xffffffff, m, off));

    if (lid == 0) swm[wid] = m;
    __syncthreads();

    if (t < 32) {
        float mm = (t < 8) ? swm[t] : NEG_INF;
        #pragma unroll
        for (int off = 4; off > 0; off >>= 1)
            mm = fmaxf(mm, __shfl_xor_sync(0xffffffff, mm, off));
        if (t == 0) s_bmax = mm;
    }
    __syncthreads();

    const float bmax = s_bmax;

    // -------- Pass 2: only winning warp(s) rescan their slice ---------------
    // Reloads are L1/L2-hot and ~1 warp per block -> negligible traffic.
    // atomicMin over flat index = exact first-occurrence argmax semantics.
    if (swm[wid] == bmax) {
        #pragma unroll
        for (int it = 0; it < QPT; ++it) {
            const int p = t + it * 256;
            const float4 v = __ldg(&src[p]);
            const int base = s * CHUNK + p * 4;
            if (v.x == bmax) atomicMin(&s_bidx, base + 0);
            if (v.y == bmax) atomicMin(&s_bidx, base + 1);
            if (v.z == bmax) atomicMin(&s_bidx, base + 2);
            if (v.w == bmax) atomicMin(&s_bidx, base + 3);
        }
    }
    __syncthreads();

    // -------- Publish partial; 64th arriver per batch finalizes -------------
    if (t == 0) {
        g_pval[bj * SPLIT + s] = bmax;
        g_pidx[bj * SPLIT + s] = s_bidx;
        __threadfence();
        const int prev = atomicAdd(&g_count[b], 1);
        s_last = (prev == BLKS_PER_B - 1) ? 1 : 0;
    }
    __syncthreads();

    if (!s_last) return;

    // ------------------- Finalize batch b: gather + MSE ---------------------
    __shared__ int s_idx[Jn];

    if (t < Jn) {
        const int base = (b * Jn + t) * SPLIT;
        float bv = NEG_INF;
        int   bi = 0x7fffffff;
        #pragma unroll
        for (int k = 0; k < SPLIT; ++k) {
            const float v = __ldcg(&g_pval[base + k]);
            const int   i = __ldcg(&g_pidx[base + k]);
            if (v > bv || (v == bv && i < bi)) { bv = v; bi = i; }
        }
        s_idx[t] = bi;
    }
    __syncthreads();

    // J*C = 1024 gathered elements, 256 threads -> 4 each
    float acc = 0.0f;
    #pragma unroll
    for (int it = 0; it < (Jn * Cn) / 256; ++it) {
        const int e = t + it * 256;
        const int j = e >> 6;        // /64
        const int c = e & 63;        // %64
        const int idx = s_idx[j];
        const float p = __ldg(&pred[((size_t)b * Cn + c) * HWn + idx]);
        const float g = __ldg(&gt[((size_t)b * Jn + j) * Cn + c]);
        const float d = p - g;
        acc += d * d;
    }

    #pragma unroll
    for (int off = 16; off > 0; off >>= 1)
        acc += __shfl_down_sync(0xffffffff, acc, off);

    __shared__ float ss[8];
    if (lid == 0) ss[wid] = acc;
    __syncthreads();
    if (t < 32) {
        acc = (lid < 8) ? ss[lid] : 0.0f;
        #pragma unroll
        for (int off = 4; off > 0; off >>= 1)
            acc += __shfl_down_sync(0xffffffff, acc, off);
        if (lid == 0) {
            out[b] = acc * (1.0f / (Jn * Cn));
            g_count[b] = 0;   // reset for next graph replay
        }
    }
}

extern "C" void kernel_launch(void* const* d_in, const int* in_sizes, int n_in,
                              void* d_out, int out_size)
{
    const float* pred    = (const float*)d_in[0];   // [B,C,H,W]
    const float* gt      = (const float*)d_in[1];   // [B,J,C]
    const float* heatmap = (const float*)d_in[2];   // [B,J,H,W]
    float* out = (float*)d_out;                     // [B]

    fused_labelloss_kernel<<<NPART, 256>>>(heatmap, pred, gt, out);
}